// round 8
// baseline (speedup 1.0000x reference)
#include <cuda_runtime.h>
#include <cuda_bf16.h>

#define BB 16
#define LL 8400
#define NG 32
#define KK 68
#define NTOPK 13
#define EPSV 1e-9f
#define CAND_CAP 1024
#define SEL_CAP 640
#define PLIST_CAP (BB * NG * NTOPK)   // 6656 exact max

// flat output offsets (float32 elements), tuple order:
// labels(B,L), bboxes(B,L,4), scores(B,L,1), poses(B,L,K,3), vertices(B,L,K,3),
// rotations(B,L,3,3), gt_index(B,L)
#define O1 134400
#define O2 672000
#define O3 806400
#define O4 28224000
#define O5 55641600
#define O6 56851200

// scratch (static __device__ globals — no runtime allocation)
__device__ unsigned int g_mask[BB * LL];   // per-anchor gt bitmask; resolved in-place by k2
__device__ int          g_maxm[BB * NG];   // per-gt max metric   (float bits, >=0)
__device__ int          g_maxiou[BB * NG]; // per-gt max iou      (float bits, >=0)
__device__ int          g_cnt[BB * NG];    // per-gt candidate count
__device__ float        g_cm[BB * NG * CAND_CAP]; // candidate metrics
__device__ int          g_ci[BB * NG * CAND_CAP]; // candidate anchor indices
__device__ int          g_pcnt;            // positive-anchor list count
__device__ int          g_plist[PLIST_CAP];// flat anchor ids with >=1 mask bit

__device__ __forceinline__ float iou_fn(float gx1, float gy1, float gx2, float gy2,
                                        float px1, float py1, float px2, float py2) {
    float ix1 = fmaxf(gx1, px1), iy1 = fmaxf(gy1, py1);
    float ix2 = fminf(gx2, px2), iy2 = fminf(gy2, py2);
    float ov = fmaxf(ix2 - ix1, 0.f) * fmaxf(iy2 - iy1, 0.f);
    float a1 = fmaxf(gx2 - gx1, 0.f) * fmaxf(gy2 - gy1, 0.f);
    float a2 = fmaxf(px2 - px1, 0.f) * fmaxf(py2 - py1, 0.f);
    return ov / (a1 + a2 - ov + EPSV);
}

__device__ __forceinline__ bool in_gts_fn(float ax, float ay, float4 g) {
    return (ax - g.x > EPSV) && (ay - g.y > EPSV) && (g.z - ax > EPSV) && (g.w - ay > EPSV);
}

// ---------------- K0: zero scratch ----------------
__global__ void k0_zero() {
    int idx = blockIdx.x * blockDim.x + threadIdx.x;
    int stride = gridDim.x * blockDim.x;
    for (int i = idx; i < BB * LL; i += stride) g_mask[i] = 0u;
    for (int i = idx; i < BB * NG; i += stride) { g_maxm[i] = 0; g_maxiou[i] = 0; g_cnt[i] = 0; }
    if (idx == 0) g_pcnt = 0;
}

// ---------------- K_cand: anchor-keyed candidate building ----------------
// Reads each anchor's pred box/score ONCE; appends (metric, l) to per-gt lists
// with warp-aggregated atomics. Candidate = in_gts && metric > 0.
__global__ void k_cand(const float* __restrict__ ps, const float* __restrict__ pb,
                       const float* __restrict__ ap, const float* __restrict__ gtb) {
    int b = blockIdx.y;
    int l = blockIdx.x * 256 + threadIdx.x;
    __shared__ float4 sg[NG];
    if (threadIdx.x < NG) sg[threadIdx.x] = ((const float4*)gtb)[b * NG + threadIdx.x];
    __syncthreads();
    bool act = (l < LL);
    int lane = threadIdx.x & 31;
    float ax = 0.f, ay = 0.f, sc = 0.f;
    float4 p = make_float4(0.f, 0.f, 0.f, 0.f);
    if (act) {
        float2 apv = ((const float2*)ap)[l];
        ax = apv.x; ay = apv.y;
        int a = b * LL + l;
        p = ((const float4*)pb)[a];
        sc = ps[a];
    }
    for (int i = 0; i < NG; i++) {
        float4 g = sg[i];
        float m = 0.f;
        if (act && in_gts_fn(ax, ay, g)) {
            float iou = iou_fn(g.x, g.y, g.z, g.w, p.x, p.y, p.z, p.w);
            float i2 = iou * iou;
            m = sc * (i2 * i2 * i2);
        }
        unsigned want = __ballot_sync(0xffffffffu, m > 0.f);
        if (want) {
            int gid = b * NG + i;
            int leader = __ffs(want) - 1;
            int base = 0;
            if (lane == leader) base = atomicAdd(&g_cnt[gid], __popc(want));
            base = __shfl_sync(0xffffffffu, base, leader);
            if (m > 0.f) {
                int pos = base + __popc(want & ((1u << lane) - 1u));
                if (pos < CAND_CAP) {
                    g_cm[gid * CAND_CAP + pos] = m;
                    g_ci[gid * CAND_CAP + pos] = l;
                }
            }
        }
    }
}

// ---------------- K_sel: warp-per-gt top-13 + positive-anchor list append ----------------
__global__ void __launch_bounds__(128) k_sel(const float* __restrict__ ap,
                                             const float* __restrict__ gtb,
                                             const float* __restrict__ pad) {
    __shared__ float sv[4][SEL_CAP];
    __shared__ int   si[4][SEL_CAP];
    int wl = threadIdx.x >> 5;
    int w  = blockIdx.x * 4 + wl;     // gt id: b*NG+gi
    int lane = threadIdx.x & 31;
    int b  = w >> 5;                  // NG == 32
    int gi = w & 31;
    if (pad[w] == 0.f) return;        // uniform over warp
    int p = min(g_cnt[w], SEL_CAP);
    int base = w * CAND_CAP;
    for (int j = lane; j < p; j += 32) { sv[wl][j] = g_cm[base + j]; si[wl][j] = g_ci[base + j]; }
    __syncwarp();
    unsigned mbase = b * LL;
    int nsel = min(p, NTOPK);
    for (int k = 0; k < nsel; k++) {
        float bv = -1.f; int bi = 1 << 30; int bj = -1;
        for (int j = lane; j < p; j += 32) {
            float v = sv[wl][j]; int idx = si[wl][j];
            if (v > bv || (v == bv && idx < bi)) { bv = v; bi = idx; bj = j; }
        }
        #pragma unroll
        for (int off = 16; off > 0; off >>= 1) {
            float ov = __shfl_down_sync(0xffffffffu, bv, off);
            int oi = __shfl_down_sync(0xffffffffu, bi, off);
            int oj = __shfl_down_sync(0xffffffffu, bj, off);
            if (ov > bv || (ov == bv && oi < bi)) { bv = ov; bi = oi; bj = oj; }
        }
        bj = __shfl_sync(0xffffffffu, bj, 0);
        bi = __shfl_sync(0xffffffffu, bi, 0);
        if (lane == 0) {
            sv[wl][bj] = -1.f;                        // remove selected
            atomicOr(&g_mask[mbase + bi], 1u << gi);  // candidates are in_gts by construction
            int pp = atomicAdd(&g_pcnt, 1);
            g_plist[pp] = (int)(mbase + bi);
        }
        __syncwarp();
    }
    if (p < NTOPK && lane == 0) {
        float4 g = ((const float4*)gtb)[w];
        int need = NTOPK - p;
        for (int l = 0; need > 0 && l < LL; l++) {
            bool ispos = false;
            for (int j = 0; j < p; j++) if (si[wl][j] == l) { ispos = true; break; }
            if (!ispos) {
                need--;
                float2 apv = ((const float2*)ap)[l];
                if (in_gts_fn(apv.x, apv.y, g)) {
                    atomicOr(&g_mask[mbase + l], 1u << gi);
                    int pp = atomicAdd(&g_pcnt, 1);
                    g_plist[pp] = (int)(mbase + l);
                }
            }
        }
    }
}

// ---------------- K2: sparse resolve over positive anchors only ----------------
// Duplicated anchors (claimed by several gts) resolve identically — benign.
// Resolved one-hot written back into g_mask in place.
__global__ void __launch_bounds__(256) k2_sparse(const float* __restrict__ ps,
                                                 const float* __restrict__ pb,
                                                 const float* __restrict__ gtb) {
    __shared__ float4 sg[BB * NG];   // all 512 gt boxes, 8KB
    for (int j = threadIdx.x; j < BB * NG; j += 256) sg[j] = ((const float4*)gtb)[j];
    __syncthreads();
    int idx = blockIdx.x * 256 + threadIdx.x;
    if (idx >= g_pcnt) return;
    int a = g_plist[idx];
    int b = a / LL;
    unsigned bits = g_mask[a];
    float4 p = ((const float4*)pb)[a];
    float sc = ps[a];
    if (__popc(bits) > 1) {
        // replace column with one-hot argmax-iou over ALL gts (first-index tiebreak)
        float bv = -1.f; int bi = 0;
        #pragma unroll
        for (int i = 0; i < NG; i++) {
            float4 g = sg[b * NG + i];
            float iou = iou_fn(g.x, g.y, g.z, g.w, p.x, p.y, p.z, p.w);
            if (iou > bv) { bv = iou; bi = i; }
        }
        bits = 1u << bi;
        g_mask[a] = bits;   // duplicates write the same value
    }
    int i = __ffs(bits) - 1;
    int gid = b * NG + i;
    float4 g = sg[gid];
    float iou = iou_fn(g.x, g.y, g.z, g.w, p.x, p.y, p.z, p.w);
    float i2 = iou * iou;
    float m = sc * (i2 * i2 * i2);
    atomicMax(&g_maxm[gid], __float_as_int(m));     // values >= 0: int order == float order
    atomicMax(&g_maxiou[gid], __float_as_int(iou));
}

// ---------------- K34: warp-per-anchor, all outputs ----------------
__global__ void __launch_bounds__(256) k34_out(
        const float* __restrict__ ps, const float* __restrict__ pb,
        const float* __restrict__ gtb, const float* __restrict__ gp,
        const float* __restrict__ gv, const float* __restrict__ grot,
        const int* __restrict__ gl, const int* __restrict__ bgp,
        float* __restrict__ out) {
    unsigned a = (blockIdx.x * 256u + threadIdx.x) >> 5;   // anchor = warp id
    int lane = threadIdx.x & 31;
    unsigned bits = g_mask[a];                 // broadcast load
    int b = a / LL;
    int i = bits ? (__ffs(bits) - 1) : 0;      // argmax of all-zero column = 0
    size_t gidx = (size_t)(b * NG + i);

    const float4* Psrc = (const float4*)gp + gidx * 51;
    const float4* Vsrc = (const float4*)gv + gidx * 51;
    float4* Pd = (float4*)(out + O3) + (size_t)a * 51;
    float4* Vd = (float4*)(out + O4) + (size_t)a * 51;

    int c0 = lane, c1 = lane + 32, c2 = lane + 64, c3 = lane + 96;
    float4 v0 = (c0 < 51) ? Psrc[c0] : Vsrc[c0 - 51];
    float4 v1 = (c1 < 51) ? Psrc[c1] : Vsrc[c1 - 51];
    float4 v2 = Vsrc[c2 - 51];
    float4 v3; bool has3 = (c3 < 102);
    float r9 = 0.f;
    if (has3) v3 = Vsrc[c3 - 51];
    if (lane < 9) r9 = grot[gidx * 9 + lane];

    if (c0 < 51) Pd[c0] = v0; else Vd[c0 - 51] = v0;
    if (c1 < 51) Pd[c1] = v1; else Vd[c1 - 51] = v1;
    Vd[c2 - 51] = v2;
    if (has3) Vd[c3 - 51] = v3;
    if (lane < 9) out[O5 + (size_t)a * 9 + lane] = r9;

    if (lane == 0) {
        int lbl = bits ? gl[gidx] : bgp[0];
        float4 gbox = ((const float4*)gtb)[gidx];
        float score = 0.f;
        if (bits) {
            float4 p = ((const float4*)pb)[a];
            float iou = iou_fn(gbox.x, gbox.y, gbox.z, gbox.w, p.x, p.y, p.z, p.w);
            float i2 = iou * iou;
            float m = ps[a] * (i2 * i2 * i2);
            float mm = __int_as_float(g_maxm[gidx]);
            float mi = __int_as_float(g_maxiou[gidx]);
            float am = m / (mm + EPSV) * mi;
            score = (lbl == 0) ? am : 0.f;  // one_hot(lbl, C+1)[..., keep=[0]]
        }
        out[a] = (float)lbl;                // assigned_labels
        ((float4*)(out + O1))[a] = gbox;    // assigned_bboxes
        out[O2 + a] = score;                // assigned_scores
        out[O6 + a] = (float)gidx;          // assigned_gt_index
    }
}

extern "C" void kernel_launch(void* const* d_in, const int* in_sizes, int n_in,
                              void* d_out, int out_size) {
    const float* ps  = (const float*)d_in[0];  // pred_scores  (B,L,1)
    const float* pb  = (const float*)d_in[1];  // pred_bboxes  (B,L,4)
    const float* ap  = (const float*)d_in[2];  // anchor_points(L,2)
    const int*   gl  = (const int*)  d_in[3];  // gt_labels
    const float* gtb = (const float*)d_in[4];  // gt_bboxes    (B,n,4)
    const float* gp  = (const float*)d_in[5];  // gt_poses     (B,n,K,3)
    const float* gv  = (const float*)d_in[6];  // gt_vertices  (B,n,K,3)
    const float* gr  = (const float*)d_in[7];  // gt_rotations (B,n,3,3)
    const float* pad = (const float*)d_in[8];  // pad_gt_mask  (B,n,1)
    const int*   bg  = (const int*)  d_in[9];  // bg_index scalar
    float* out = (float*)d_out;

    dim3 ga((LL + 255) / 256, BB);
    k0_zero<<<132, 256>>>();
    k_cand<<<ga, 256>>>(ps, pb, ap, gtb);
    k_sel<<<BB * NG / 4, 128>>>(ap, gtb, pad);
    k2_sparse<<<(PLIST_CAP + 255) / 256, 256>>>(ps, pb, gtb);   // 26 blocks
    // 134400 anchors = 134400 warps = 16800 blocks of 8 warps, exact
    k34_out<<<16800, 256>>>(ps, pb, gtb, gp, gv, gr, gl, bg, out);
}